// round 4
// baseline (speedup 1.0000x reference)
#include <cuda_runtime.h>
#include <math.h>
#include <stdint.h>

#define Dd 256
#define Vv 3000
#define Tt 50
#define Kk 50
#define Ll 300
#define THh 800
#define EHh 200

// ---------------- scratch (__device__ globals; no allocations) --------------
static __device__ float g_P[12800 * 3000];   // exp(logits)
static __device__ float g_A[12800 * 300];
static __device__ float g_S[12800];          // softmax denominators
static __device__ float g_x[50 * 200];
static __device__ float g_xw0[50 * 800];
static __device__ float g_xw1[50 * 800];
static __device__ float g_hs0[50 * 200];
static __device__ float g_hs1[50 * 200];
static __device__ float g_etas[50 * 50];
static __device__ float g_cat[256 * 3050];
static __device__ float g_h1[256 * 800];
static __device__ float g_h2[256 * 800];
static __device__ float g_muth[256 * 50];
static __device__ float g_lsth[256 * 50];
static __device__ float g_theta[256 * 50];
static __device__ float g_scalars[4];        // 0:+sum(log*bows) 1:kl_a 2:kl_eta 3:kl_th

// ---------------- fast exp on FMA pipe (avoid MUFU throughput wall) ---------
__device__ __forceinline__ float fexp_fast(float x) {
    float y = x * 1.4426950408889634f;
    y = fminf(fmaxf(y, -80.f), 80.f);
    float r = rintf(y);
    float f = y - r;
    float p = 1.3333558e-3f;
    p = fmaf(p, f, 9.6181291e-3f);
    p = fmaf(p, f, 5.5504109e-2f);
    p = fmaf(p, f, 2.4022651e-1f);
    p = fmaf(p, f, 6.9314718e-1f);
    p = fmaf(p, f, 1.0f);
    return p * __int_as_float(((int)r + 127) << 23);
}

__device__ __forceinline__ float blockReduceSum(float v, float* sm) {
    int tid = threadIdx.x;
    sm[tid] = v; __syncthreads();
    for (int off = blockDim.x >> 1; off > 0; off >>= 1) {
        if (tid < off) sm[tid] += sm[tid + off];
        __syncthreads();
    }
    return sm[0];
}

// ---------------- zero scratch ----------------------------------------------
__global__ void zeroAllK() {
    int stride = gridDim.x * blockDim.x;
    for (int i = blockIdx.x * blockDim.x + threadIdx.x; i < 204800; i += stride) {
        g_h1[i] = 0.f; g_h2[i] = 0.f;
        if (i < 40000) { g_xw0[i] = 0.f; g_xw1[i] = 0.f; }
        if (i < 12800) { g_S[i] = 0.f; g_muth[i] = 0.f; g_lsth[i] = 0.f; }
        if (i < 10000) g_x[i] = 0.f;
        if (i < 4) g_scalars[i] = 0.f;
    }
}

// ---------------- kl_alpha --------------------------------------------------
__global__ void klAlphaK(const float* __restrict__ mu, const float* __restrict__ ls) {
    __shared__ float sm[256];
    const float logdelta = logf(0.005f);
    const float invdel = 1.f / (__expf(logdelta) + 1e-6f);
    int stride = gridDim.x * blockDim.x;
    float acc = 0.f;
    for (int i = blockIdx.x * blockDim.x + threadIdx.x; i < Kk * Tt * Ll; i += stride) {
        int t = (i / Ll) % Tt;
        float qm = mu[i], ql = ls[i];
        if (t == 0) {
            acc += (__expf(ql) + qm * qm) / (1.f + 1e-6f) - 1.f - ql;
        } else {
            float pm = mu[i - Ll];
            float d = qm - pm;
            acc += (__expf(ql) + d * d) * invdel - 1.f + logdelta - ql;
        }
    }
    float tot = blockReduceSum(acc, sm);
    if (threadIdx.x == 0) atomicAdd(&g_scalars[1], 0.5f * tot);
}

// ---------------- generic tiled GEMM (NN, split-K atomic) -------------------
// C(M,N) += A(M,Kd) @ B(Kd,N), split-K chunk per blockIdx.z
__global__ void gemmNN(const float* __restrict__ A, const float* __restrict__ B,
                       float* __restrict__ C, int M, int N, int Kd, int kchunk) {
    __shared__ float As[16][64];
    __shared__ float Bs[16][64];
    int tid = threadIdx.x;
    int tx = tid & 15, ty = tid >> 4;
    int row0 = blockIdx.y * 64, col0 = blockIdx.x * 64;
    int kbeg = blockIdx.z * kchunk;
    int kend = min(Kd, kbeg + kchunk);
    int aRow = tid >> 2, aCol = (tid & 3) << 2;
    int bRow = tid >> 4, bCol = (tid & 15) << 2;
    float acc[4][4] = {};
    for (int k0 = kbeg; k0 < kend; k0 += 16) {
#pragma unroll
        for (int i = 0; i < 4; i++) {
            int kk = k0 + aCol + i, r = row0 + aRow;
            As[aCol + i][aRow] = (r < M && kk < kend) ? A[(size_t)r * Kd + kk] : 0.f;
        }
#pragma unroll
        for (int i = 0; i < 4; i++) {
            int kk = k0 + bRow, n = col0 + bCol + i;
            Bs[bRow][bCol + i] = (n < N && kk < kend) ? B[(size_t)kk * N + n] : 0.f;
        }
        __syncthreads();
#pragma unroll
        for (int kk = 0; kk < 16; kk++) {
            float a[4], b[4];
#pragma unroll
            for (int i = 0; i < 4; i++) a[i] = As[kk][ty * 4 + i];
#pragma unroll
            for (int j = 0; j < 4; j++) b[j] = Bs[kk][tx * 4 + j];
#pragma unroll
            for (int i = 0; i < 4; i++)
#pragma unroll
                for (int j = 0; j < 4; j++) acc[i][j] = fmaf(a[i], b[j], acc[i][j]);
        }
        __syncthreads();
    }
#pragma unroll
    for (int i = 0; i < 4; i++) {
        int r = row0 + ty * 4 + i;
        if (r >= M) continue;
#pragma unroll
        for (int j = 0; j < 4; j++) {
            int c = col0 + tx * 4 + j;
            if (c >= N) continue;
            if (gridDim.z > 1) atomicAdd(&C[(size_t)r * N + c], acc[i][j]);
            else C[(size_t)r * N + c] = acc[i][j];
        }
    }
}

// ---------------- big NT GEMM with exp epilogue + row sums ------------------
// P(M,N) = exp(A(M,Kd) @ B(N,Kd)^T), rowsum[r] += sum_c P[r][c]
__global__ void gemmExpNT(const float* __restrict__ A, const float* __restrict__ B,
                          float* __restrict__ P, float* __restrict__ rowsum,
                          int M, int N, int Kd) {
    __shared__ float As[16][64];
    __shared__ float Bs[16][64];
    int tid = threadIdx.x;
    int tx = tid & 15, ty = tid >> 4;
    int row0 = blockIdx.y * 64, col0 = blockIdx.x * 64;
    int aRow = tid >> 2, aCol = (tid & 3) << 2;
    float acc[4][4] = {};
    for (int k0 = 0; k0 < Kd; k0 += 16) {
#pragma unroll
        for (int i = 0; i < 4; i++) {
            int kk = k0 + aCol + i, r = row0 + aRow;
            As[aCol + i][aRow] = (r < M && kk < Kd) ? A[(size_t)r * Kd + kk] : 0.f;
        }
#pragma unroll
        for (int i = 0; i < 4; i++) {
            int kk = k0 + aCol + i, n = col0 + aRow;
            Bs[aCol + i][aRow] = (n < N && kk < Kd) ? B[(size_t)n * Kd + kk] : 0.f;
        }
        __syncthreads();
#pragma unroll
        for (int kk = 0; kk < 16; kk++) {
            float a[4], b[4];
#pragma unroll
            for (int i = 0; i < 4; i++) a[i] = As[kk][ty * 4 + i];
#pragma unroll
            for (int j = 0; j < 4; j++) b[j] = Bs[kk][tx * 4 + j];
#pragma unroll
            for (int i = 0; i < 4; i++)
#pragma unroll
                for (int j = 0; j < 4; j++) acc[i][j] = fmaf(a[i], b[j], acc[i][j]);
        }
        __syncthreads();
    }
    float rs[4] = {0.f, 0.f, 0.f, 0.f};
#pragma unroll
    for (int i = 0; i < 4; i++) {
        int r = row0 + ty * 4 + i;
#pragma unroll
        for (int j = 0; j < 4; j++) {
            int c = col0 + tx * 4 + j;
            if (r < M && c < N) {
                float p = fexp_fast(acc[i][j]);
                P[(size_t)r * N + c] = p;
                rs[i] += p;
            }
        }
    }
#pragma unroll
    for (int off = 8; off >= 1; off >>= 1)
#pragma unroll
        for (int i = 0; i < 4; i++) rs[i] += __shfl_xor_sync(0xffffffffu, rs[i], off);
    if (tx == 0) {
#pragma unroll
        for (int i = 0; i < 4; i++) {
            int r = row0 + ty * 4 + i;
            if (r < M) atomicAdd(&rowsum[r], rs[i]);
        }
    }
}

// ---------------- bias (+optional relu) -------------------------------------
__global__ void biasActK(float* __restrict__ C, const float* __restrict__ b,
                         int M, int N, int relu) {
    int stride = gridDim.x * blockDim.x;
    for (int i = blockIdx.x * blockDim.x + threadIdx.x; i < M * N; i += stride) {
        float v = C[i] + b[i % N];
        if (relu) v = fmaxf(v, 0.f);
        C[i] = v;
    }
}

// ---------------- LSTM layer: 4-CTA cluster, Whh sliced in smem -------------
#define LSTM_SMEM ((200 * 200 + 200 + 200) * 4)

__device__ __forceinline__ unsigned ctarank_() {
    unsigned r; asm("mov.u32 %0, %%cluster_ctarank;" : "=r"(r)); return r;
}
__device__ __forceinline__ void cluster_sync_() {
    asm volatile("barrier.cluster.arrive.aligned;" ::: "memory");
    asm volatile("barrier.cluster.wait.aligned;" ::: "memory");
}
__device__ __forceinline__ void dsmem_st(uint32_t laddr, unsigned r, float v) {
    uint32_t ra;
    asm volatile("mapa.shared::cluster.u32 %0, %1, %2;" : "=r"(ra) : "r"(laddr), "r"(r));
    asm volatile("st.shared::cluster.f32 [%0], %1;" :: "r"(ra), "f"(v) : "memory");
}
__device__ __forceinline__ float sigmoidf_(float x) { return 1.f / (1.f + __expf(-x)); }

__global__ void __launch_bounds__(256, 1) __cluster_dims__(4, 1, 1)
lstmK(const float* __restrict__ xw, const float* __restrict__ Whh,
      float* __restrict__ hs) {
    extern __shared__ float sm[];
    float* Wsl = sm;              // [200][200]: Wsl[e*200+j]
    float* h   = sm + 40000;      // full 200-cell hidden state (replicated)
    float* gbuf = sm + 40200;     // this CTA's 200 gate values
    int tid = threadIdx.x;
    unsigned rank = ctarank_();

    // thread j handles gate column col(j) = (j/50)*200 + rank*50 + (j%50)
    int q = tid / 50, cl = tid % 50;
    int col = q * 200 + (int)rank * 50 + cl;   // valid for tid<200

    for (int idx = tid; idx < 200 * 200; idx += blockDim.x) {
        int e = idx / 200, j = idx % 200;
        int cj = (j / 50) * 200 + (int)rank * 50 + (j % 50);
        Wsl[idx] = Whh[e * 800 + cj];
    }
    if (tid < 200) h[tid] = 0.f;
    float c = 0.f;                // cell state, thread tid<50 owns cell rank*50+tid
    __syncthreads();
    cluster_sync_();

    uint32_t haddr_base = (uint32_t)__cvta_generic_to_shared(h);

    for (int t = 0; t < Tt; t++) {
        if (tid < 200) {
            float gv = xw[t * 800 + col];
#pragma unroll 4
            for (int e = 0; e < 200; e++) gv = fmaf(h[e], Wsl[e * 200 + tid], gv);
            gbuf[tid] = gv;
        }
        __syncthreads();
        if (tid < 50) {
            float gi = gbuf[tid], gf = gbuf[50 + tid], gg = gbuf[100 + tid], go = gbuf[150 + tid];
            c = sigmoidf_(gf) * c + sigmoidf_(gi) * tanhf(gg);
            float h2 = sigmoidf_(go) * tanhf(c);
            int e = (int)rank * 50 + tid;
            hs[t * 200 + e] = h2;
            uint32_t la = haddr_base + (uint32_t)(e * 4);
#pragma unroll
            for (unsigned r2 = 0; r2 < 4; r2++) dsmem_st(la, r2, h2);
        }
        cluster_sync_();
    }
}

// ---------------- eta scan (sequential, 1 block) ----------------------------
__global__ void etaScanK(const float* __restrict__ hs1,
                         const float* __restrict__ Wmu, const float* __restrict__ bmu,
                         const float* __restrict__ Wls, const float* __restrict__ bls) {
    __shared__ float eta[50], outt[200], part[5][100], muv[50], lsv[50], red[50];
    __shared__ float klacc;
    int tid = threadIdx.x;
    if (tid < 50) eta[tid] = 0.f;
    if (tid == 0) klacc = 0.f;
    const float logdelta = logf(0.005f);
    __syncthreads();
    for (int t = 0; t < Tt; t++) {
        if (tid < 200) outt[tid] = hs1[t * 200 + tid];
        __syncthreads();
        if (tid < 500) {
            int p = tid / 100, idx = tid % 100, colk = idx % 50;
            const float* W = (idx >= 50) ? Wls : Wmu;
            float s = 0.f;
#pragma unroll 5
            for (int j = p * 50; j < p * 50 + 50; j++) {
                float cv = (j < 200) ? outt[j] : eta[j - 200];
                s = fmaf(cv, W[j * 50 + colk], s);
            }
            part[p][idx] = s;
        }
        __syncthreads();
        if (tid < 100) {
            int colk = tid % 50;
            float s = part[0][tid] + part[1][tid] + part[2][tid] + part[3][tid] + part[4][tid];
            if (tid >= 50) lsv[colk] = s + bls[colk];
            else           muv[colk] = s + bmu[colk];
        }
        __syncthreads();
        if (tid < 50) {
            float pls = (t == 0) ? 0.f : logdelta;
            float mu = muv[tid], ls = lsv[tid], ep = eta[tid];
            float dm = mu - ep;
            red[tid] = (__expf(ls) + dm * dm) / (__expf(pls) + 1e-6f) - 1.f + pls - ls;
            g_etas[t * 50 + tid] = mu;
        }
        __syncthreads();
        if (tid == 0) {
            float s = 0.f;
            for (int i = 0; i < 50; i++) s += red[i];
            klacc += 0.5f * s;
        }
        if (tid < 50) eta[tid] = muv[tid];
        __syncthreads();
    }
    if (tid == 0) g_scalars[2] = klacc;
}

// ---------------- build cat = [bows | eta_td] -------------------------------
__global__ void buildCatK(const float* __restrict__ bows, const int* __restrict__ times) {
    int stride = gridDim.x * blockDim.x;
    for (int i = blockIdx.x * blockDim.x + threadIdx.x; i < Dd * 3050; i += stride) {
        int d = i / 3050, j = i % 3050;
        g_cat[i] = (j < Vv) ? bows[d * Vv + j] : g_etas[times[d] * 50 + (j - Vv)];
    }
}

// ---------------- theta softmax + kl_theta ----------------------------------
__global__ void thetaKlK(const int* __restrict__ times) {
    int d = blockIdx.x, tid = threadIdx.x;
    __shared__ float sm[64];
    float mu = (tid < 50) ? g_muth[d * 50 + tid] : -1e30f;
    sm[tid] = mu; __syncthreads();
    for (int off = 32; off > 0; off >>= 1) {
        if (tid < off) sm[tid] = fmaxf(sm[tid], sm[tid + off]);
        __syncthreads();
    }
    float m = sm[0]; __syncthreads();
    float e = (tid < 50) ? __expf(mu - m) : 0.f;
    sm[tid] = e; __syncthreads();
    for (int off = 32; off > 0; off >>= 1) {
        if (tid < off) sm[tid] += sm[tid + off];
        __syncthreads();
    }
    float Z = sm[0]; __syncthreads();
    if (tid < 50) g_theta[d * 50 + tid] = e / Z;
    float term = 0.f;
    if (tid < 50) {
        float ls = g_lsth[d * 50 + tid];
        float et = g_etas[times[d] * 50 + tid];
        float dm = mu - et;
        term = (__expf(ls) + dm * dm) / (1.f + 1e-6f) - 1.f - ls;
    }
    sm[tid] = term; __syncthreads();
    for (int off = 32; off > 0; off >>= 1) {
        if (tid < off) sm[tid] += sm[tid + off];
        __syncthreads();
    }
    if (tid == 0) atomicAdd(&g_scalars[3], 0.5f * sm[0]);
}

// ---------------- build A rows: alpha[k,t_d,:]*lam[s_d,:] -------------------
__global__ void buildAK(const float* __restrict__ alpha, const float* __restrict__ lam,
                        const int* __restrict__ times, const int* __restrict__ sources) {
    int stride = gridDim.x * blockDim.x;
    for (int i = blockIdx.x * blockDim.x + threadIdx.x; i < 12800 * Ll; i += stride) {
        int r = i / Ll, l = i % Ll;
        int d = r / Kk, k = r % Kk;
        g_A[i] = alpha[(k * Tt + times[d]) * Ll + l] * lam[sources[d] * Ll + l];
    }
}

// ---------------- lik + nll -------------------------------------------------
__global__ void likNllK(const float* __restrict__ bows) {
    __shared__ float w[50];
    __shared__ float sm[256];
    int d = blockIdx.y, tid = threadIdx.x;
    if (tid < 50) w[tid] = g_theta[d * 50 + tid] / g_S[d * 50 + tid];
    __syncthreads();
    int v = blockIdx.x * 256 + tid;
    float acc = 0.f;
    if (v < Vv) {
        const float* Pr = g_P + (size_t)d * 50 * Vv + v;
        float lik = 0.f;
#pragma unroll 10
        for (int k = 0; k < 50; k++) lik = fmaf(w[k], Pr[(size_t)k * Vv], lik);
        acc = __logf(lik + 1e-6f) * bows[d * Vv + v];
    }
    float tot = blockReduceSum(acc, sm);
    if (tid == 0) atomicAdd(&g_scalars[0], tot);
}

__global__ void finalizeK(float* __restrict__ out) {
    if (threadIdx.x == 0) {
        out[0] = -g_scalars[0];
        out[1] = g_scalars[1];
        out[2] = g_scalars[2];
        out[3] = g_scalars[3];
    }
}

// ---------------- host orchestration ----------------------------------------
extern "C" void kernel_launch(void* const* d_in, const int* in_sizes, int n_in,
                              void* d_out, int out_size) {
    const float* bows    = (const float*)d_in[0];
    const float* rnn_inp = (const float*)d_in[1];
    const int*   times   = (const int*)d_in[2];
    const int*   sources = (const int*)d_in[3];
    const float* rho     = (const float*)d_in[4];
    const float* lam     = (const float*)d_in[5];
    const float* mu_q    = (const float*)d_in[6];
    const float* ls_q    = (const float*)d_in[7];
    const float* W_t1    = (const float*)d_in[8];
    const float* b_t1    = (const float*)d_in[9];
    const float* W_t2    = (const float*)d_in[10];
    const float* b_t2    = (const float*)d_in[11];
    const float* W_mu_th = (const float*)d_in[12];
    const float* b_mu_th = (const float*)d_in[13];
    const float* W_ls_th = (const float*)d_in[14];
    const float* b_ls_th = (const float*)d_in[15];
    const float* W_em    = (const float*)d_in[16];
    const float* b_em    = (const float*)d_in[17];
    const float* Wih0    = (const float*)d_in[18];
    const float* Whh0    = (const float*)d_in[19];
    const float* bl0     = (const float*)d_in[20];
    const float* Wih1    = (const float*)d_in[21];
    const float* Whh1    = (const float*)d_in[22];
    const float* bl1     = (const float*)d_in[23];
    const float* W_mu_e  = (const float*)d_in[24];
    const float* b_mu_e  = (const float*)d_in[25];
    const float* W_ls_e  = (const float*)d_in[26];
    const float* b_ls_e  = (const float*)d_in[27];

    float *pX, *pXw0, *pXw1, *pHs0, *pHs1, *pCat, *pH1, *pH2, *pMuth, *pLsth, *pA, *pP, *pS;
    cudaGetSymbolAddress((void**)&pX, g_x);
    cudaGetSymbolAddress((void**)&pXw0, g_xw0);
    cudaGetSymbolAddress((void**)&pXw1, g_xw1);
    cudaGetSymbolAddress((void**)&pHs0, g_hs0);
    cudaGetSymbolAddress((void**)&pHs1, g_hs1);
    cudaGetSymbolAddress((void**)&pCat, g_cat);
    cudaGetSymbolAddress((void**)&pH1, g_h1);
    cudaGetSymbolAddress((void**)&pH2, g_h2);
    cudaGetSymbolAddress((void**)&pMuth, g_muth);
    cudaGetSymbolAddress((void**)&pLsth, g_lsth);
    cudaGetSymbolAddress((void**)&pA, g_A);
    cudaGetSymbolAddress((void**)&pP, g_P);
    cudaGetSymbolAddress((void**)&pS, g_S);

    cudaFuncSetAttribute(lstmK, cudaFuncAttributeMaxDynamicSharedMemorySize, LSTM_SMEM);

    zeroAllK<<<256, 256>>>();
    klAlphaK<<<256, 256>>>(mu_q, ls_q);

    // x = rnn_inp @ W_em + b_em
    gemmNN<<<dim3(4, 1, 8), 256>>>(rnn_inp, W_em, pX, 50, 200, 3000, 384);
    biasActK<<<40, 256>>>(pX, b_em, 50, 200, 0);

    // LSTM layer 0
    gemmNN<<<dim3(13, 1, 1), 256>>>(pX, Wih0, pXw0, 50, 800, 200, 200);
    biasActK<<<160, 256>>>(pXw0, bl0, 50, 800, 0);
    lstmK<<<4, 256, LSTM_SMEM>>>(pXw0, Whh0, pHs0);

    // LSTM layer 1
    gemmNN<<<dim3(13, 1, 1), 256>>>(pHs0, Wih1, pXw1, 50, 800, 200, 200);
    biasActK<<<160, 256>>>(pXw1, bl1, 50, 800, 0);
    lstmK<<<4, 256, LSTM_SMEM>>>(pXw1, Whh1, pHs1);

    // eta scan
    etaScanK<<<1, 512>>>(pHs1, W_mu_e, b_mu_e, W_ls_e, b_ls_e);

    // theta MLP
    buildCatK<<<1024, 256>>>(bows, times);
    gemmNN<<<dim3(13, 4, 4), 256>>>(pCat, W_t1, pH1, 256, 800, 3050, 768);
    biasActK<<<800, 256>>>(pH1, b_t1, 256, 800, 1);
    gemmNN<<<dim3(13, 4, 2), 256>>>(pH1, W_t2, pH2, 256, 800, 800, 400);
    biasActK<<<800, 256>>>(pH2, b_t2, 256, 800, 1);
    gemmNN<<<dim3(1, 4, 8), 256>>>(pH2, W_mu_th, pMuth, 256, 50, 800, 112);
    biasActK<<<50, 256>>>(pMuth, b_mu_th, 256, 50, 0);
    gemmNN<<<dim3(1, 4, 8), 256>>>(pH2, W_ls_th, pLsth, 256, 50, 800, 112);
    biasActK<<<50, 256>>>(pLsth, b_ls_th, 256, 50, 0);
    thetaKlK<<<256, 64>>>(times);

    // big einsum: P = exp(A @ rho^T), rowsums, then lik/nll
    buildAK<<<2048, 256>>>(mu_q, lam, times, sources);
    gemmExpNT<<<dim3(47, 200), 256>>>(pA, rho, pP, pS, 12800, 3000, 300);
    likNllK<<<dim3(12, 256), 256>>>(bows);

    finalizeK<<<1, 32>>>((float*)d_out);
}

// round 6
// speedup vs baseline: 1.1146x; 1.1146x over previous
#include <cuda_runtime.h>
#include <cuda_bf16.h>
#include <math.h>
#include <stdint.h>

#define Dd 256
#define Vv 3000
#define Tt 50
#define Kk 50
#define Ll 300
#define LPAD 320

// ---------------- scratch (__device__ globals; no allocations) --------------
static __device__ float g_P[12800 * 3000];                       // exp(logits)
static __device__ __align__(16) __nv_bfloat16 g_Abf[12800 * LPAD];
static __device__ __align__(16) __nv_bfloat16 g_rhoBf[3000 * LPAD];
static __device__ float g_S[12800];          // softmax denominators
static __device__ float g_x[50 * 200];
static __device__ float g_xw0[50 * 800];
static __device__ float g_xw1[50 * 800];
static __device__ float g_hs0[50 * 200];
static __device__ float g_hs1[50 * 200];
static __device__ float g_etas[50 * 50];
static __device__ float g_cat[256 * 3050];
static __device__ float g_h1[256 * 800];
static __device__ float g_h2[256 * 800];
static __device__ float g_muth[256 * 50];
static __device__ float g_lsth[256 * 50];
static __device__ float g_theta[256 * 50];
static __device__ float g_scalars[4];        // 0:+sum(log*bows) 1:kl_a 2:kl_eta 3:kl_th

// ---------------- fast exp on FMA pipe --------------------------------------
__device__ __forceinline__ float fexp_fast(float x) {
    float y = x * 1.4426950408889634f;
    float r = rintf(y);
    float f = y - r;
    float p = 1.3333558e-3f;
    p = fmaf(p, f, 9.6181291e-3f);
    p = fmaf(p, f, 5.5504109e-2f);
    p = fmaf(p, f, 2.4022651e-1f);
    p = fmaf(p, f, 6.9314718e-1f);
    p = fmaf(p, f, 1.0f);
    return p * __int_as_float(((int)r + 127) << 23);
}

__device__ __forceinline__ float blockReduceSum(float v, float* sm) {
    int tid = threadIdx.x;
    sm[tid] = v; __syncthreads();
    for (int off = blockDim.x >> 1; off > 0; off >>= 1) {
        if (tid < off) sm[tid] += sm[tid + off];
        __syncthreads();
    }
    return sm[0];
}

// ---------------- big GEMM on HMMA (mma.sync bf16) + exp epilogue -----------
// P(12800,3000) = exp(Abf(12800,320) @ rhoBf(3000,320)^T), rowsum += per-row
#define ASTRIDE 40   // bf16 elements per smem row (80B -> conflict-free ldmatrix)

__global__ void __launch_bounds__(256, 1) gemmExpMMA(
    const __nv_bfloat16* __restrict__ Abf, const __nv_bfloat16* __restrict__ Bbf,
    float* __restrict__ P, float* __restrict__ rowsum) {
    __shared__ __align__(16) __nv_bfloat16 A_sm[128 * ASTRIDE];
    __shared__ __align__(16) __nv_bfloat16 B_sm[128 * ASTRIDE];

    const int tid = threadIdx.x;
    const int wid = tid >> 5, lane = tid & 31;
    const int warp_m = wid >> 2, warp_n = wid & 3;   // 2 x 4 warp grid
    const int m_base = warp_m * 64, n_base = warp_n * 32;

    const int row0 = blockIdx.y * 128;
    const int col0 = blockIdx.x * 128;

    float acc[4][4][4];
#pragma unroll
    for (int i = 0; i < 4; i++)
#pragma unroll
        for (int j = 0; j < 4; j++)
#pragma unroll
            for (int e = 0; e < 4; e++) acc[i][j][e] = 0.f;

    // ldmatrix source addresses (fixed per thread, plus k-chunk offset)
    const uint32_t aBase = (uint32_t)__cvta_generic_to_shared(A_sm);
    const uint32_t bBase = (uint32_t)__cvta_generic_to_shared(B_sm);

    for (int c = 0; c < LPAD / 32; c++) {
        const int k0 = c * 32;
        __syncthreads();
        // load A,B 128x32 bf16 tiles: 512 uint4 each, 2 per thread per operand
#pragma unroll
        for (int it = 0; it < 2; it++) {
            int idx = tid + it * 256;
            int r = idx >> 2, seg = idx & 3;          // seg: 8 bf16 = 16B
            // A (rows always valid; 12800 % 128 == 0)
            *(uint4*)&A_sm[r * ASTRIDE + seg * 8] =
                *(const uint4*)&Abf[(size_t)(row0 + r) * LPAD + k0 + seg * 8];
            // B (guard n < Vv)
            int n = col0 + r;
            uint4 vb = make_uint4(0u, 0u, 0u, 0u);
            if (n < Vv)
                vb = *(const uint4*)&Bbf[(size_t)n * LPAD + k0 + seg * 8];
            *(uint4*)&B_sm[r * ASTRIDE + seg * 8] = vb;
        }
        __syncthreads();

#pragma unroll
        for (int kk = 0; kk < 2; kk++) {             // two k16 steps per chunk
            uint32_t afr[4][4], bfr[4][2];
#pragma unroll
            for (int mi = 0; mi < 4; mi++) {
                uint32_t addr = aBase + (uint32_t)(((m_base + mi * 16 + (lane & 15)) * ASTRIDE
                                 + kk * 16 + (lane >> 4) * 8) * 2);
                asm volatile(
                    "ldmatrix.sync.aligned.m8n8.x4.shared.b16 {%0,%1,%2,%3}, [%4];"
                    : "=r"(afr[mi][0]), "=r"(afr[mi][1]), "=r"(afr[mi][2]), "=r"(afr[mi][3])
                    : "r"(addr));
            }
#pragma unroll
            for (int ni = 0; ni < 4; ni++) {
                uint32_t addr = bBase + (uint32_t)(((n_base + ni * 8 + (lane & 7)) * ASTRIDE
                                 + kk * 16 + ((lane >> 3) & 1) * 8) * 2);
                asm volatile(
                    "ldmatrix.sync.aligned.m8n8.x2.shared.b16 {%0,%1}, [%2];"
                    : "=r"(bfr[ni][0]), "=r"(bfr[ni][1])
                    : "r"(addr));
            }
#pragma unroll
            for (int mi = 0; mi < 4; mi++)
#pragma unroll
                for (int ni = 0; ni < 4; ni++) {
                    asm volatile(
                        "mma.sync.aligned.m16n8k16.row.col.f32.bf16.bf16.f32 "
                        "{%0,%1,%2,%3}, {%4,%5,%6,%7}, {%8,%9}, {%0,%1,%2,%3};"
                        : "+f"(acc[mi][ni][0]), "+f"(acc[mi][ni][1]),
                          "+f"(acc[mi][ni][2]), "+f"(acc[mi][ni][3])
                        : "r"(afr[mi][0]), "r"(afr[mi][1]), "r"(afr[mi][2]), "r"(afr[mi][3]),
                          "r"(bfr[ni][0]), "r"(bfr[ni][1]));
                }
        }
    }

    // Epilogue: exp + stores + row sums.
    // c0,c1 -> row = lane/4,      cols = (lane%4)*2 + {0,1}
    // c2,c3 -> row = lane/4 + 8,  same cols
    const int g = lane >> 2, q = lane & 3;
#pragma unroll
    for (int mi = 0; mi < 4; mi++) {
        float rsLo = 0.f, rsHi = 0.f;   // rows r and r+8
        int rLo = row0 + m_base + mi * 16 + g;
#pragma unroll
        for (int ni = 0; ni < 4; ni++) {
            int col = col0 + n_base + ni * 8 + q * 2;
            if (col < Vv) {
                float e0 = fexp_fast(acc[mi][ni][0]);
                float e1 = fexp_fast(acc[mi][ni][1]);
                float e2 = fexp_fast(acc[mi][ni][2]);
                float e3 = fexp_fast(acc[mi][ni][3]);
                rsLo += e0 + e1;
                rsHi += e2 + e3;
                *(float2*)&P[(size_t)rLo * Vv + col] = make_float2(e0, e1);
                *(float2*)&P[(size_t)(rLo + 8) * Vv + col] = make_float2(e2, e3);
            }
        }
        // reduce across the 4 lanes sharing a row (lane%4)
        rsLo += __shfl_xor_sync(0xffffffffu, rsLo, 1);
        rsLo += __shfl_xor_sync(0xffffffffu, rsLo, 2);
        rsHi += __shfl_xor_sync(0xffffffffu, rsHi, 1);
        rsHi += __shfl_xor_sync(0xffffffffu, rsHi, 2);
        if (q == 0) {
            atomicAdd(&rowsum[rLo], rsLo);
            atomicAdd(&rowsum[rLo + 8], rsHi);
        }
    }
}

// ---------------- build bf16 operands ---------------------------------------
__global__ void buildABfK(const float* __restrict__ alpha, const float* __restrict__ lam,
                          const int* __restrict__ times, const int* __restrict__ sources) {
    int stride = gridDim.x * blockDim.x;
    for (int i = blockIdx.x * blockDim.x + threadIdx.x; i < 12800 * LPAD; i += stride) {
        int r = i / LPAD, l = i - r * LPAD;
        int d = r / Kk, k = r - d * Kk;
        float v = 0.f;
        if (l < Ll)
            v = alpha[((size_t)k * Tt + times[d]) * Ll + l] * lam[(size_t)sources[d] * Ll + l];
        g_Abf[i] = __float2bfloat16(v);
    }
}

__global__ void rhoBfK(const float* __restrict__ rho) {
    int stride = gridDim.x * blockDim.x;
    for (int i = blockIdx.x * blockDim.x + threadIdx.x; i < Vv * LPAD; i += stride) {
        int r = i / LPAD, l = i - r * LPAD;
        g_rhoBf[i] = __float2bfloat16(l < Ll ? rho[(size_t)r * Ll + l] : 0.f);
    }
}

// ---------------- zero scratch ----------------------------------------------
__global__ void zeroAllK() {
    int stride = gridDim.x * blockDim.x;
    for (int i = blockIdx.x * blockDim.x + threadIdx.x; i < 204800; i += stride) {
        g_h1[i] = 0.f; g_h2[i] = 0.f;
        if (i < 40000) { g_xw0[i] = 0.f; g_xw1[i] = 0.f; }
        if (i < 12800) { g_S[i] = 0.f; g_muth[i] = 0.f; g_lsth[i] = 0.f; }
        if (i < 10000) g_x[i] = 0.f;
        if (i < 4) g_scalars[i] = 0.f;
    }
}

// ---------------- kl_alpha --------------------------------------------------
__global__ void klAlphaK(const float* __restrict__ mu, const float* __restrict__ ls) {
    __shared__ float sm[256];
    const float logdelta = logf(0.005f);
    const float invdel = 1.f / (__expf(logdelta) + 1e-6f);
    int stride = gridDim.x * blockDim.x;
    float acc = 0.f;
    for (int i = blockIdx.x * blockDim.x + threadIdx.x; i < Kk * Tt * Ll; i += stride) {
        int t = (i / Ll) % Tt;
        float qm = mu[i], ql = ls[i];
        if (t == 0) {
            acc += (__expf(ql) + qm * qm) / (1.f + 1e-6f) - 1.f - ql;
        } else {
            float pm = mu[i - Ll];
            float d = qm - pm;
            acc += (__expf(ql) + d * d) * invdel - 1.f + logdelta - ql;
        }
    }
    float tot = blockReduceSum(acc, sm);
    if (threadIdx.x == 0) atomicAdd(&g_scalars[1], 0.5f * tot);
}

// ---------------- generic tiled GEMM (NN, split-K atomic) -------------------
__global__ void gemmNN(const float* __restrict__ A, const float* __restrict__ B,
                       float* __restrict__ C, int M, int N, int Kd, int kchunk) {
    __shared__ float As[16][64];
    __shared__ float Bs[16][64];
    int tid = threadIdx.x;
    int tx = tid & 15, ty = tid >> 4;
    int row0 = blockIdx.y * 64, col0 = blockIdx.x * 64;
    int kbeg = blockIdx.z * kchunk;
    int kend = min(Kd, kbeg + kchunk);
    int aRow = tid >> 2, aCol = (tid & 3) << 2;
    int bRow = tid >> 4, bCol = (tid & 15) << 2;
    float acc[4][4] = {};
    for (int k0 = kbeg; k0 < kend; k0 += 16) {
#pragma unroll
        for (int i = 0; i < 4; i++) {
            int kk = k0 + aCol + i, r = row0 + aRow;
            As[aCol + i][aRow] = (r < M && kk < kend) ? A[(size_t)r * Kd + kk] : 0.f;
        }
#pragma unroll
        for (int i = 0; i < 4; i++) {
            int kk = k0 + bRow, n = col0 + bCol + i;
            Bs[bRow][bCol + i] = (n < N && kk < kend) ? B[(size_t)kk * N + n] : 0.f;
        }
        __syncthreads();
#pragma unroll
        for (int kk = 0; kk < 16; kk++) {
            float a[4], b[4];
#pragma unroll
            for (int i = 0; i < 4; i++) a[i] = As[kk][ty * 4 + i];
#pragma unroll
            for (int j = 0; j < 4; j++) b[j] = Bs[kk][tx * 4 + j];
#pragma unroll
            for (int i = 0; i < 4; i++)
#pragma unroll
                for (int j = 0; j < 4; j++) acc[i][j] = fmaf(a[i], b[j], acc[i][j]);
        }
        __syncthreads();
    }
#pragma unroll
    for (int i = 0; i < 4; i++) {
        int r = row0 + ty * 4 + i;
        if (r >= M) continue;
#pragma unroll
        for (int j = 0; j < 4; j++) {
            int c = col0 + tx * 4 + j;
            if (c >= N) continue;
            if (gridDim.z > 1) atomicAdd(&C[(size_t)r * N + c], acc[i][j]);
            else C[(size_t)r * N + c] = acc[i][j];
        }
    }
}

// ---------------- bias (+optional relu) -------------------------------------
__global__ void biasActK(float* __restrict__ C, const float* __restrict__ b,
                         int M, int N, int relu) {
    int stride = gridDim.x * blockDim.x;
    for (int i = blockIdx.x * blockDim.x + threadIdx.x; i < M * N; i += stride) {
        float v = C[i] + b[i % N];
        if (relu) v = fmaxf(v, 0.f);
        C[i] = v;
    }
}

// ---------------- LSTM layer: 4-CTA cluster, Whh sliced in smem -------------
#define LSTM_SMEM ((200 * 200 + 200 + 200) * 4)

__device__ __forceinline__ unsigned ctarank_() {
    unsigned r; asm("mov.u32 %0, %%cluster_ctarank;" : "=r"(r)); return r;
}
__device__ __forceinline__ void cluster_sync_() {
    asm volatile("barrier.cluster.arrive.aligned;" ::: "memory");
    asm volatile("barrier.cluster.wait.aligned;" ::: "memory");
}
__device__ __forceinline__ void dsmem_st(uint32_t laddr, unsigned r, float v) {
    uint32_t ra;
    asm volatile("mapa.shared::cluster.u32 %0, %1, %2;" : "=r"(ra) : "r"(laddr), "r"(r));
    asm volatile("st.shared::cluster.f32 [%0], %1;" :: "r"(ra), "f"(v) : "memory");
}
__device__ __forceinline__ float sigmoidf_(float x) { return 1.f / (1.f + __expf(-x)); }

__global__ void __launch_bounds__(256, 1) __cluster_dims__(4, 1, 1)
lstmK(const float* __restrict__ xw, const float* __restrict__ Whh,
      float* __restrict__ hs) {
    extern __shared__ float sm[];
    float* Wsl = sm;
    float* h   = sm + 40000;
    float* gbuf = sm + 40200;
    int tid = threadIdx.x;
    unsigned rank = ctarank_();

    int q = tid / 50, cl = tid % 50;
    int col = q * 200 + (int)rank * 50 + cl;

    for (int idx = tid; idx < 200 * 200; idx += blockDim.x) {
        int e = idx / 200, j = idx % 200;
        int cj = (j / 50) * 200 + (int)rank * 50 + (j % 50);
        Wsl[idx] = Whh[e * 800 + cj];
    }
    if (tid < 200) h[tid] = 0.f;
    float c = 0.f;
    __syncthreads();
    cluster_sync_();

    uint32_t haddr_base = (uint32_t)__cvta_generic_to_shared(h);

    for (int t = 0; t < Tt; t++) {
        if (tid < 200) {
            float gv = xw[t * 800 + col];
#pragma unroll 4
            for (int e = 0; e < 200; e++) gv = fmaf(h[e], Wsl[e * 200 + tid], gv);
            gbuf[tid] = gv;
        }
        __syncthreads();
        if (tid < 50) {
            float gi = gbuf[tid], gf = gbuf[50 + tid], gg = gbuf[100 + tid], go = gbuf[150 + tid];
            c = sigmoidf_(gf) * c + sigmoidf_(gi) * tanhf(gg);
            float h2 = sigmoidf_(go) * tanhf(c);
            int e = (int)rank * 50 + tid;
            hs[t * 200 + e] = h2;
            uint32_t la = haddr_base + (uint32_t)(e * 4);
#pragma unroll
            for (unsigned r2 = 0; r2 < 4; r2++) dsmem_st(la, r2, h2);
        }
        cluster_sync_();
    }
}

// ---------------- eta scan (sequential, 1 block) ----------------------------
__global__ void etaScanK(const float* __restrict__ hs1,
                         const float* __restrict__ Wmu, const float* __restrict__ bmu,
                         const float* __restrict__ Wls, const float* __restrict__ bls) {
    __shared__ float eta[50], outt[200], part[5][100], muv[50], lsv[50], red[50];
    __shared__ float klacc;
    int tid = threadIdx.x;
    if (tid < 50) eta[tid] = 0.f;
    if (tid == 0) klacc = 0.f;
    const float logdelta = logf(0.005f);
    __syncthreads();
    for (int t = 0; t < Tt; t++) {
        if (tid < 200) outt[tid] = hs1[t * 200 + tid];
        __syncthreads();
        if (tid < 500) {
            int p = tid / 100, idx = tid % 100, colk = idx % 50;
            const float* W = (idx >= 50) ? Wls : Wmu;
            float s = 0.f;
#pragma unroll 5
            for (int j = p * 50; j < p * 50 + 50; j++) {
                float cv = (j < 200) ? outt[j] : eta[j - 200];
                s = fmaf(cv, W[j * 50 + colk], s);
            }
            part[p][idx] = s;
        }
        __syncthreads();
        if (tid < 100) {
            int colk = tid % 50;
            float s = part[0][tid] + part[1][tid] + part[2][tid] + part[3][tid] + part[4][tid];
            if (tid >= 50) lsv[colk] = s + bls[colk];
            else           muv[colk] = s + bmu[colk];
        }
        __syncthreads();
        if (tid < 50) {
            float pls = (t == 0) ? 0.f : logdelta;
            float mu = muv[tid], ls = lsv[tid], ep = eta[tid];
            float dm = mu - ep;
            red[tid] = (__expf(ls) + dm * dm) / (__expf(pls) + 1e-6f) - 1.f + pls - ls;
            g_etas[t * 50 + tid] = mu;
        }
        __syncthreads();
        if (tid == 0) {
            float s = 0.f;
            for (int i = 0; i < 50; i++) s += red[i];
            klacc += 0.5f * s;
        }
        if (tid < 50) eta[tid] = muv[tid];
        __syncthreads();
    }
    if (tid == 0) g_scalars[2] = klacc;
}

// ---------------- build cat = [bows | eta_td] -------------------------------
__global__ void buildCatK(const float* __restrict__ bows, const int* __restrict__ times) {
    int stride = gridDim.x * blockDim.x;
    for (int i = blockIdx.x * blockDim.x + threadIdx.x; i < Dd * 3050; i += stride) {
        int d = i / 3050, j = i % 3050;
        g_cat[i] = (j < Vv) ? bows[d * Vv + j] : g_etas[times[d] * 50 + (j - Vv)];
    }
}

// ---------------- theta softmax + kl_theta ----------------------------------
__global__ void thetaKlK(const int* __restrict__ times) {
    int d = blockIdx.x, tid = threadIdx.x;
    __shared__ float sm[64];
    float mu = (tid < 50) ? g_muth[d * 50 + tid] : -1e30f;
    sm[tid] = mu; __syncthreads();
    for (int off = 32; off > 0; off >>= 1) {
        if (tid < off) sm[tid] = fmaxf(sm[tid], sm[tid + off]);
        __syncthreads();
    }
    float m = sm[0]; __syncthreads();
    float e = (tid < 50) ? __expf(mu - m) : 0.f;
    sm[tid] = e; __syncthreads();
    for (int off = 32; off > 0; off >>= 1) {
        if (tid < off) sm[tid] += sm[tid + off];
        __syncthreads();
    }
    float Z = sm[0]; __syncthreads();
    if (tid < 50) g_theta[d * 50 + tid] = e / Z;
    float term = 0.f;
    if (tid < 50) {
        float ls = g_lsth[d * 50 + tid];
        float et = g_etas[times[d] * 50 + tid];
        float dm = mu - et;
        term = (__expf(ls) + dm * dm) / (1.f + 1e-6f) - 1.f - ls;
    }
    sm[tid] = term; __syncthreads();
    for (int off = 32; off > 0; off >>= 1) {
        if (tid < off) sm[tid] += sm[tid + off];
        __syncthreads();
    }
    if (tid == 0) atomicAdd(&g_scalars[3], 0.5f * sm[0]);
}

// ---------------- lik + nll -------------------------------------------------
__global__ void likNllK(const float* __restrict__ bows) {
    __shared__ float w[50];
    __shared__ float sm[256];
    int d = blockIdx.y, tid = threadIdx.x;
    if (tid < 50) w[tid] = g_theta[d * 50 + tid] / g_S[d * 50 + tid];
    __syncthreads();
    int v = blockIdx.x * 256 + tid;
    float acc = 0.f;
    if (v < Vv) {
        const float* Pr = g_P + (size_t)d * 50 * Vv + v;
        float lik = 0.f;
#pragma unroll 10
        for (int k = 0; k < 50; k++) lik = fmaf(w[k], Pr[(size_t)k * Vv], lik);
        acc = __logf(lik + 1e-6f) * bows[d * Vv + v];
    }
    float tot = blockReduceSum(acc, sm);
    if (tid == 0) atomicAdd(&g_scalars[0], tot);
}

__global__ void finalizeK(float* __restrict__ out) {
    if (threadIdx.x == 0) {
        out[0] = -g_scalars[0];
        out[1] = g_scalars[1];
        out[2] = g_scalars[2];
        out[3] = g_scalars[3];
    }
}

// ---------------- host orchestration ----------------------------------------
extern "C" void kernel_launch(void* const* d_in, const int* in_sizes, int n_in,
                              void* d_out, int out_size) {
    const float* bows    = (const float*)d_in[0];
    const float* rnn_inp = (const float*)d_in[1];
    const int*   times   = (const int*)d_in[2];
    const int*   sources = (const int*)d_in[3];
    const float* rho     = (const float*)d_in[4];
    const float* lam     = (const float*)d_in[5];
    const float* mu_q    = (const float*)d_in[6];
    const float* ls_q    = (const float*)d_in[7];
    const float* W_t1    = (const float*)d_in[8];
    const float* b_t1    = (const float*)d_in[9];
    const float* W_t2    = (const float*)d_in[10];
    const float* b_t2    = (const float*)d_in[11];
    const float* W_mu_th = (const float*)d_in[12];
    const float* b_mu_th = (const float*)d_in[13];
    const float* W_ls_th = (const float*)d_in[14];
    const float* b_ls_th = (const float*)d_in[15];
    const float* W_em    = (const float*)d_in[16];
    const float* b_em    = (const float*)d_in[17];
    const float* Wih0    = (const float*)d_in[18];
    const float* Whh0    = (const float*)d_in[19];
    const float* bl0     = (const float*)d_in[20];
    const float* Wih1    = (const float*)d_in[21];
    const float* Whh1    = (const float*)d_in[22];
    const float* bl1     = (const float*)d_in[23];
    const float* W_mu_e  = (const float*)d_in[24];
    const float* b_mu_e  = (const float*)d_in[25];
    const float* W_ls_e  = (const float*)d_in[26];
    const float* b_ls_e  = (const float*)d_in[27];

    float *pX, *pXw0, *pXw1, *pHs0, *pHs1, *pCat, *pH1, *pH2, *pMuth, *pLsth, *pP, *pS;
    __nv_bfloat16 *pAbf, *pRhoBf;
    cudaGetSymbolAddress((void**)&pX, g_x);
    cudaGetSymbolAddress((void**)&pXw0, g_xw0);
    cudaGetSymbolAddress((void**)&pXw1, g_xw1);
    cudaGetSymbolAddress((void**)&pHs0, g_hs0);
    cudaGetSymbolAddress((void**)&pHs1, g_hs1);
    cudaGetSymbolAddress((void**)&pCat, g_cat);
    cudaGetSymbolAddress((void**)&pH1, g_h1);
    cudaGetSymbolAddress((void**)&pH2, g_h2);
    cudaGetSymbolAddress((void**)&pMuth, g_muth);
    cudaGetSymbolAddress((void**)&pLsth, g_lsth);
    cudaGetSymbolAddress((void**)&pP, g_P);
    cudaGetSymbolAddress((void**)&pS, g_S);
    cudaGetSymbolAddress((void**)&pAbf, g_Abf);
    cudaGetSymbolAddress((void**)&pRhoBf, g_rhoBf);

    cudaFuncSetAttribute(lstmK, cudaFuncAttributeMaxDynamicSharedMemorySize, LSTM_SMEM);

    zeroAllK<<<256, 256>>>();
    klAlphaK<<<256, 256>>>(mu_q, ls_q);

    // bf16 operand prep for the big GEMM
    buildABfK<<<2048, 256>>>(mu_q, lam, times, sources);
    rhoBfK<<<512, 256>>>(rho);

    // x = rnn_inp @ W_em + b_em
    gemmNN<<<dim3(4, 1, 8), 256>>>(rnn_inp, W_em, pX, 50, 200, 3000, 384);
    biasActK<<<40, 256>>>(pX, b_em, 50, 200, 0);

    // LSTM layer 0
    gemmNN<<<dim3(13, 1, 1), 256>>>(pX, Wih0, pXw0, 50, 800, 200, 200);
    biasActK<<<160, 256>>>(pXw0, bl0, 50, 800, 0);
    lstmK<<<4, 256, LSTM_SMEM>>>(pXw0, Whh0, pHs0);

    // LSTM layer 1
    gemmNN<<<dim3(13, 1, 1), 256>>>(pHs0, Wih1, pXw1, 50, 800, 200, 200);
    biasActK<<<160, 256>>>(pXw1, bl1, 50, 800, 0);
    lstmK<<<4, 256, LSTM_SMEM>>>(pXw1, Whh1, pHs1);

    // eta scan
    etaScanK<<<1, 512>>>(pHs1, W_mu_e, b_mu_e, W_ls_e, b_ls_e);

    // theta MLP
    buildCatK<<<1024, 256>>>(bows, times);
    gemmNN<<<dim3(13, 4, 4), 256>>>(pCat, W_t1, pH1, 256, 800, 3050, 768);
    biasActK<<<800, 256>>>(pH1, b_t1, 256, 800, 1);
    gemmNN<<<dim3(13, 4, 2), 256>>>(pH1, W_t2, pH2, 256, 800, 800, 400);
    biasActK<<<800, 256>>>(pH2, b_t2, 256, 800, 1);
    gemmNN<<<dim3(1, 4, 8), 256>>>(pH2, W_mu_th, pMuth, 256, 50, 800, 112);
    biasActK<<<50, 256>>>(pMuth, b_mu_th, 256, 50, 0);
    gemmNN<<<dim3(1, 4, 8), 256>>>(pH2, W_ls_th, pLsth, 256, 50, 800, 112);
    biasActK<<<50, 256>>>(pLsth, b_ls_th, 256, 50, 0);
    thetaKlK<<<256, 64>>>(times);

    // big einsum on tensor cores (mma.sync bf16): P = exp(Abf @ rhoBf^T)
    gemmExpMMA<<<dim3(24, 100), 256>>>(pAbf, pRhoBf, pP, pS);
    likNllK<<<dim3(12, 256), 256>>>(bows);

    finalizeK<<<1, 32>>>((float*)d_out);
}

// round 7
// speedup vs baseline: 1.9653x; 1.7633x over previous
#include <cuda_runtime.h>
#include <cuda_bf16.h>
#include <math.h>
#include <stdint.h>

#define Dd 256
#define Vv 3000
#define Tt 50
#define Kk 50
#define Ll 300
#define LPAD 320

// ---------------- scratch (__device__ globals; no allocations) --------------
static __device__ float g_P[12800 * 3000];                       // exp(logits)
static __device__ __align__(16) __nv_bfloat16 g_Abf[12800 * LPAD];
static __device__ __align__(16) __nv_bfloat16 g_rhoBf[3000 * LPAD];
static __device__ float g_S[12800];          // softmax denominators
static __device__ float g_x[50 * 200];
static __device__ float g_xw0[50 * 800];
static __device__ float g_xw1[50 * 800];
static __device__ float g_hs0[50 * 200];
static __device__ float g_hs1[50 * 200];
static __device__ float g_etas[50 * 50];
static __device__ float g_cat[256 * 3050];
static __device__ float g_h1[256 * 800];
static __device__ float g_h2[256 * 800];
static __device__ float g_muth[256 * 50];
static __device__ float g_lsth[256 * 50];
static __device__ float g_theta[256 * 50];
static __device__ float g_scalars[4];        // 0:+sum(log*bows) 1:kl_a 2:kl_eta 3:kl_th

// ---------------- fast exp on FMA pipe --------------------------------------
__device__ __forceinline__ float fexp_fast(float x) {
    float y = x * 1.4426950408889634f;
    float r = rintf(y);
    float f = y - r;
    float p = 1.3333558e-3f;
    p = fmaf(p, f, 9.6181291e-3f);
    p = fmaf(p, f, 5.5504109e-2f);
    p = fmaf(p, f, 2.4022651e-1f);
    p = fmaf(p, f, 6.9314718e-1f);
    p = fmaf(p, f, 1.0f);
    return p * __int_as_float(((int)r + 127) << 23);
}

__device__ __forceinline__ float blockReduceSum(float v, float* sm) {
    int tid = threadIdx.x;
    sm[tid] = v; __syncthreads();
    for (int off = blockDim.x >> 1; off > 0; off >>= 1) {
        if (tid < off) sm[tid] += sm[tid + off];
        __syncthreads();
    }
    return sm[0];
}

// ---------------- big GEMM on HMMA (mma.sync bf16) + exp epilogue -----------
// P(12800,3000) = exp(Abf(12800,320) @ rhoBf(3000,320)^T), rowsum += per-row
// Full-K resident in smem: one load phase, one sync, 20 uninterrupted k16 steps.
#define BSTR 328   // bf16 row stride: 656B -> ldmatrix rows start at bank 4r (conflict-free)
#define GEMM_SMEM (2 * 128 * BSTR * 2)

extern __shared__ __nv_bfloat16 dynsm[];

__global__ void __launch_bounds__(256, 1) gemmExpMMA(
    const __nv_bfloat16* __restrict__ Abf, const __nv_bfloat16* __restrict__ Bbf,
    float* __restrict__ P, float* __restrict__ rowsum) {
    __nv_bfloat16* A_sm = dynsm;
    __nv_bfloat16* B_sm = dynsm + 128 * BSTR;

    const int tid = threadIdx.x;
    const int wid = tid >> 5, lane = tid & 31;
    const int warp_m = wid >> 2, warp_n = wid & 3;   // 2 x 4 warp grid
    const int m_base = warp_m * 64, n_base = warp_n * 32;

    const int row0 = blockIdx.y * 128;
    const int col0 = blockIdx.x * 128;

    // ---- load full 128 x 320 tiles (5120 uint4 each, 20 per thread) ----
#pragma unroll
    for (int it = 0; it < 20; it++) {
        int idx = tid + it * 256;
        int r = idx / 40, seg = idx - r * 40;        // 40 x 16B per row
        *(uint4*)&A_sm[r * BSTR + seg * 8] =
            *(const uint4*)&Abf[(size_t)(row0 + r) * LPAD + seg * 8];
        int n = col0 + r;
        uint4 vb = make_uint4(0u, 0u, 0u, 0u);
        if (n < Vv)
            vb = *(const uint4*)&Bbf[(size_t)n * LPAD + seg * 8];
        *(uint4*)&B_sm[r * BSTR + seg * 8] = vb;
    }
    __syncthreads();

    const uint32_t aBase = (uint32_t)__cvta_generic_to_shared(A_sm);
    const uint32_t bBase = (uint32_t)__cvta_generic_to_shared(B_sm);

    float acc[4][4][4];
#pragma unroll
    for (int i = 0; i < 4; i++)
#pragma unroll
        for (int j = 0; j < 4; j++)
#pragma unroll
            for (int e = 0; e < 4; e++) acc[i][j][e] = 0.f;

#pragma unroll
    for (int ks = 0; ks < 20; ks++) {                // 20 k16 steps
        uint32_t afr[4][4], bfr[4][2];
#pragma unroll
        for (int mi = 0; mi < 4; mi++) {
            uint32_t addr = aBase + (uint32_t)(((m_base + mi * 16 + (lane & 15)) * BSTR
                             + ks * 16 + (lane >> 4) * 8) * 2);
            asm volatile(
                "ldmatrix.sync.aligned.m8n8.x4.shared.b16 {%0,%1,%2,%3}, [%4];"
                : "=r"(afr[mi][0]), "=r"(afr[mi][1]), "=r"(afr[mi][2]), "=r"(afr[mi][3])
                : "r"(addr));
        }
#pragma unroll
        for (int ni = 0; ni < 4; ni++) {
            uint32_t addr = bBase + (uint32_t)(((n_base + ni * 8 + (lane & 7)) * BSTR
                             + ks * 16 + ((lane >> 3) & 1) * 8) * 2);
            asm volatile(
                "ldmatrix.sync.aligned.m8n8.x2.shared.b16 {%0,%1}, [%2];"
                : "=r"(bfr[ni][0]), "=r"(bfr[ni][1])
                : "r"(addr));
        }
#pragma unroll
        for (int mi = 0; mi < 4; mi++)
#pragma unroll
            for (int ni = 0; ni < 4; ni++) {
                asm volatile(
                    "mma.sync.aligned.m16n8k16.row.col.f32.bf16.bf16.f32 "
                    "{%0,%1,%2,%3}, {%4,%5,%6,%7}, {%8,%9}, {%0,%1,%2,%3};"
                    : "+f"(acc[mi][ni][0]), "+f"(acc[mi][ni][1]),
                      "+f"(acc[mi][ni][2]), "+f"(acc[mi][ni][3])
                    : "r"(afr[mi][0]), "r"(afr[mi][1]), "r"(afr[mi][2]), "r"(afr[mi][3]),
                      "r"(bfr[ni][0]), "r"(bfr[ni][1]));
            }
    }

    // Epilogue: exp + stores + row sums.
    const int g = lane >> 2, q = lane & 3;
#pragma unroll
    for (int mi = 0; mi < 4; mi++) {
        float rsLo = 0.f, rsHi = 0.f;
        int rLo = row0 + m_base + mi * 16 + g;
#pragma unroll
        for (int ni = 0; ni < 4; ni++) {
            int col = col0 + n_base + ni * 8 + q * 2;
            if (col < Vv) {
                float e0 = fexp_fast(acc[mi][ni][0]);
                float e1 = fexp_fast(acc[mi][ni][1]);
                float e2 = fexp_fast(acc[mi][ni][2]);
                float e3 = fexp_fast(acc[mi][ni][3]);
                rsLo += e0 + e1;
                rsHi += e2 + e3;
                *(float2*)&P[(size_t)rLo * Vv + col] = make_float2(e0, e1);
                *(float2*)&P[(size_t)(rLo + 8) * Vv + col] = make_float2(e2, e3);
            }
        }
        rsLo += __shfl_xor_sync(0xffffffffu, rsLo, 1);
        rsLo += __shfl_xor_sync(0xffffffffu, rsLo, 2);
        rsHi += __shfl_xor_sync(0xffffffffu, rsHi, 1);
        rsHi += __shfl_xor_sync(0xffffffffu, rsHi, 2);
        if (q == 0) {
            atomicAdd(&rowsum[rLo], rsLo);
            atomicAdd(&rowsum[rLo + 8], rsHi);
        }
    }
}

// ---------------- build bf16 operands ---------------------------------------
__global__ void buildABfK(const float* __restrict__ alpha, const float* __restrict__ lam,
                          const int* __restrict__ times, const int* __restrict__ sources) {
    int stride = gridDim.x * blockDim.x;
    for (int i = blockIdx.x * blockDim.x + threadIdx.x; i < 12800 * LPAD; i += stride) {
        int r = i / LPAD, l = i - r * LPAD;
        int d = r / Kk, k = r - d * Kk;
        float v = 0.f;
        if (l < Ll)
            v = alpha[((size_t)k * Tt + times[d]) * Ll + l] * lam[(size_t)sources[d] * Ll + l];
        g_Abf[i] = __float2bfloat16(v);
    }
}

__global__ void rhoBfK(const float* __restrict__ rho) {
    int stride = gridDim.x * blockDim.x;
    for (int i = blockIdx.x * blockDim.x + threadIdx.x; i < Vv * LPAD; i += stride) {
        int r = i / LPAD, l = i - r * LPAD;
        g_rhoBf[i] = __float2bfloat16(l < Ll ? rho[(size_t)r * Ll + l] : 0.f);
    }
}

// ---------------- zero scratch ----------------------------------------------
__global__ void zeroAllK() {
    int stride = gridDim.x * blockDim.x;
    for (int i = blockIdx.x * blockDim.x + threadIdx.x; i < 204800; i += stride) {
        g_h1[i] = 0.f; g_h2[i] = 0.f;
        if (i < 40000) { g_xw0[i] = 0.f; g_xw1[i] = 0.f; }
        if (i < 12800) { g_S[i] = 0.f; g_muth[i] = 0.f; g_lsth[i] = 0.f; }
        if (i < 10000) g_x[i] = 0.f;
        if (i < 4) g_scalars[i] = 0.f;
    }
}

// ---------------- kl_alpha --------------------------------------------------
__global__ void klAlphaK(const float* __restrict__ mu, const float* __restrict__ ls) {
    __shared__ float sm[256];
    const float logdelta = logf(0.005f);
    const float invdel = 1.f / (__expf(logdelta) + 1e-6f);
    int stride = gridDim.x * blockDim.x;
    float acc = 0.f;
    for (int i = blockIdx.x * blockDim.x + threadIdx.x; i < Kk * Tt * Ll; i += stride) {
        int t = (i / Ll) % Tt;
        float qm = mu[i], ql = ls[i];
        if (t == 0) {
            acc += (__expf(ql) + qm * qm) / (1.f + 1e-6f) - 1.f - ql;
        } else {
            float pm = mu[i - Ll];
            float d = qm - pm;
            acc += (__expf(ql) + d * d) * invdel - 1.f + logdelta - ql;
        }
    }
    float tot = blockReduceSum(acc, sm);
    if (threadIdx.x == 0) atomicAdd(&g_scalars[1], 0.5f * tot);
}

// ---------------- generic tiled GEMM (NN, split-K atomic) -------------------
__global__ void gemmNN(const float* __restrict__ A, const float* __restrict__ B,
                       float* __restrict__ C, int M, int N, int Kd, int kchunk) {
    __shared__ float As[16][64];
    __shared__ float Bs[16][64];
    int tid = threadIdx.x;
    int tx = tid & 15, ty = tid >> 4;
    int row0 = blockIdx.y * 64, col0 = blockIdx.x * 64;
    int kbeg = blockIdx.z * kchunk;
    int kend = min(Kd, kbeg + kchunk);
    int aRow = tid >> 2, aCol = (tid & 3) << 2;
    int bRow = tid >> 4, bCol = (tid & 15) << 2;
    float acc[4][4] = {};
    for (int k0 = kbeg; k0 < kend; k0 += 16) {
#pragma unroll
        for (int i = 0; i < 4; i++) {
            int kk = k0 + aCol + i, r = row0 + aRow;
            As[aCol + i][aRow] = (r < M && kk < kend) ? A[(size_t)r * Kd + kk] : 0.f;
        }
#pragma unroll
        for (int i = 0; i < 4; i++) {
            int kk = k0 + bRow, n = col0 + bCol + i;
            Bs[bRow][bCol + i] = (n < N && kk < kend) ? B[(size_t)kk * N + n] : 0.f;
        }
        __syncthreads();
#pragma unroll
        for (int kk = 0; kk < 16; kk++) {
            float a[4], b[4];
#pragma unroll
            for (int i = 0; i < 4; i++) a[i] = As[kk][ty * 4 + i];
#pragma unroll
            for (int j = 0; j < 4; j++) b[j] = Bs[kk][tx * 4 + j];
#pragma unroll
            for (int i = 0; i < 4; i++)
#pragma unroll
                for (int j = 0; j < 4; j++) acc[i][j] = fmaf(a[i], b[j], acc[i][j]);
        }
        __syncthreads();
    }
#pragma unroll
    for (int i = 0; i < 4; i++) {
        int r = row0 + ty * 4 + i;
        if (r >= M) continue;
#pragma unroll
        for (int j = 0; j < 4; j++) {
            int c = col0 + tx * 4 + j;
            if (c >= N) continue;
            if (gridDim.z > 1) atomicAdd(&C[(size_t)r * N + c], acc[i][j]);
            else C[(size_t)r * N + c] = acc[i][j];
        }
    }
}

// ---------------- bias (+optional relu) -------------------------------------
__global__ void biasActK(float* __restrict__ C, const float* __restrict__ b,
                         int M, int N, int relu) {
    int stride = gridDim.x * blockDim.x;
    for (int i = blockIdx.x * blockDim.x + threadIdx.x; i < M * N; i += stride) {
        float v = C[i] + b[i % N];
        if (relu) v = fmaxf(v, 0.f);
        C[i] = v;
    }
}

// ---------------- LSTM layer: 4-CTA cluster, Whh sliced in smem -------------
#define LSTM_SMEM ((200 * 200 + 200 + 200) * 4)

__device__ __forceinline__ unsigned ctarank_() {
    unsigned r; asm("mov.u32 %0, %%cluster_ctarank;" : "=r"(r)); return r;
}
__device__ __forceinline__ void cluster_sync_() {
    asm volatile("barrier.cluster.arrive.aligned;" ::: "memory");
    asm volatile("barrier.cluster.wait.aligned;" ::: "memory");
}
__device__ __forceinline__ void dsmem_st(uint32_t laddr, unsigned r, float v) {
    uint32_t ra;
    asm volatile("mapa.shared::cluster.u32 %0, %1, %2;" : "=r"(ra) : "r"(laddr), "r"(r));
    asm volatile("st.shared::cluster.f32 [%0], %1;" :: "r"(ra), "f"(v) : "memory");
}
__device__ __forceinline__ float sigmoidf_(float x) { return 1.f / (1.f + __expf(-x)); }

__global__ void __launch_bounds__(256, 1) __cluster_dims__(4, 1, 1)
lstmK(const float* __restrict__ xw, const float* __restrict__ Whh,
      float* __restrict__ hs) {
    extern __shared__ float sm[];
    float* Wsl = sm;
    float* h   = sm + 40000;
    float* gbuf = sm + 40200;
    int tid = threadIdx.x;
    unsigned rank = ctarank_();

    int q = tid / 50, cl = tid % 50;
    int col = q * 200 + (int)rank * 50 + cl;

    for (int idx = tid; idx < 200 * 200; idx += blockDim.x) {
        int e = idx / 200, j = idx % 200;
        int cj = (j / 50) * 200 + (int)rank * 50 + (j % 50);
        Wsl[idx] = Whh[e * 800 + cj];
    }
    if (tid < 200) h[tid] = 0.f;
    float c = 0.f;
    __syncthreads();
    cluster_sync_();

    uint32_t haddr_base = (uint32_t)__cvta_generic_to_shared(h);

    for (int t = 0; t < Tt; t++) {
        if (tid < 200) {
            float gv = xw[t * 800 + col];
#pragma unroll 4
            for (int e = 0; e < 200; e++) gv = fmaf(h[e], Wsl[e * 200 + tid], gv);
            gbuf[tid] = gv;
        }
        __syncthreads();
        if (tid < 50) {
            float gi = gbuf[tid], gf = gbuf[50 + tid], gg = gbuf[100 + tid], go = gbuf[150 + tid];
            c = sigmoidf_(gf) * c + sigmoidf_(gi) * tanhf(gg);
            float h2 = sigmoidf_(go) * tanhf(c);
            int e = (int)rank * 50 + tid;
            hs[t * 200 + e] = h2;
            uint32_t la = haddr_base + (uint32_t)(e * 4);
#pragma unroll
            for (unsigned r2 = 0; r2 < 4; r2++) dsmem_st(la, r2, h2);
        }
        cluster_sync_();
    }
}

// ---------------- eta scan (sequential, 1 block, W cached in smem) ----------
#define ETA_SMEM (2 * 250 * 50 * 4)

__global__ void etaScanK(const float* __restrict__ hs1,
                         const float* __restrict__ Wmu, const float* __restrict__ bmu,
                         const float* __restrict__ Wls, const float* __restrict__ bls) {
    extern __shared__ float esm[];
    float* sWmu = esm;               // 250*50
    float* sWls = esm + 12500;       // 250*50
    __shared__ float eta[50], outt[200], part[5][100], muv[50], lsv[50], red[50];
    __shared__ float klacc;
    int tid = threadIdx.x;
    for (int i = tid; i < 12500; i += blockDim.x) { sWmu[i] = Wmu[i]; sWls[i] = Wls[i]; }
    if (tid < 50) eta[tid] = 0.f;
    if (tid == 0) klacc = 0.f;
    const float logdelta = logf(0.005f);
    __syncthreads();
    for (int t = 0; t < Tt; t++) {
        if (tid < 200) outt[tid] = hs1[t * 200 + tid];
        __syncthreads();
        if (tid < 500) {
            int p = tid / 100, idx = tid % 100, colk = idx % 50;
            const float* W = (idx >= 50) ? sWls : sWmu;
            float s = 0.f;
#pragma unroll 5
            for (int j = p * 50; j < p * 50 + 50; j++) {
                float cv = (j < 200) ? outt[j] : eta[j - 200];
                s = fmaf(cv, W[j * 50 + colk], s);
            }
            part[p][idx] = s;
        }
        __syncthreads();
        if (tid < 100) {
            int colk = tid % 50;
            float s = part[0][tid] + part[1][tid] + part[2][tid] + part[3][tid] + part[4][tid];
            if (tid >= 50) lsv[colk] = s + bls[colk];
            else           muv[colk] = s + bmu[colk];
        }
        __syncthreads();
        if (tid < 50) {
            float pls = (t == 0) ? 0.f : logdelta;
            float mu = muv[tid], ls = lsv[tid], ep = eta[tid];
            float dm = mu - ep;
            red[tid] = (__expf(ls) + dm * dm) / (__expf(pls) + 1e-6f) - 1.f + pls - ls;
            g_etas[t * 50 + tid] = mu;
        }
        __syncthreads();
        if (tid == 0) {
            float s = 0.f;
            for (int i = 0; i < 50; i++) s += red[i];
            klacc += 0.5f * s;
        }
        if (tid < 50) eta[tid] = muv[tid];
        __syncthreads();
    }
    if (tid == 0) g_scalars[2] = klacc;
}

// ---------------- build cat = [bows | eta_td] -------------------------------
__global__ void buildCatK(const float* __restrict__ bows, const int* __restrict__ times) {
    int stride = gridDim.x * blockDim.x;
    for (int i = blockIdx.x * blockDim.x + threadIdx.x; i < Dd * 3050; i += stride) {
        int d = i / 3050, j = i % 3050;
        g_cat[i] = (j < Vv) ? bows[d * Vv + j] : g_etas[times[d] * 50 + (j - Vv)];
    }
}

// ---------------- theta softmax + kl_theta ----------------------------------
__global__ void thetaKlK(const int* __restrict__ times) {
    int d = blockIdx.x, tid = threadIdx.x;
    __shared__ float sm[64];
    float mu = (tid < 50) ? g_muth[d * 50 + tid] : -1e30f;
    sm[tid] = mu; __syncthreads();
    for (int off = 32; off > 0; off >>= 1) {
        if (tid < off) sm[tid] = fmaxf(sm[tid], sm[tid + off]);
        __syncthreads();
    }
    float m = sm[0]; __syncthreads();
    float e = (tid < 50) ? __expf(mu - m) : 0.f;
    sm[tid] = e; __syncthreads();
    for (int off = 32; off > 0; off >>= 1) {
        if (tid < off) sm[tid] += sm[tid + off];
        __syncthreads();
    }
    float Z = sm[0]; __syncthreads();
    if (tid < 50) g_theta[d * 50 + tid] = e / Z;
    float term = 0.f;
    if (tid < 50) {
        float ls = g_lsth[d * 50 + tid];
        float et = g_etas[times[d] * 50 + tid];
        float dm = mu - et;
        term = (__expf(ls) + dm * dm) / (1.f + 1e-6f) - 1.f - ls;
    }
    sm[tid] = term; __syncthreads();
    for (int off = 32; off > 0; off >>= 1) {
        if (tid < off) sm[tid] += sm[tid + off];
        __syncthreads();
    }
    if (tid == 0) atomicAdd(&g_scalars[3], 0.5f * sm[0]);
}

// ---------------- lik + nll -------------------------------------------------
__global__ void likNllK(const float* __restrict__ bows) {
    __shared__ float w[50];
    __shared__ float sm[256];
    int d = blockIdx.y, tid = threadIdx.x;
    if (tid < 50) w[tid] = g_theta[d * 50 + tid] / g_S[d * 50 + tid];
    __syncthreads();
    int v = blockIdx.x * 256 + tid;
    float acc = 0.f;
    if (v < Vv) {
        const float* Pr = g_P + (size_t)d * 50 * Vv + v;
        float lik = 0.f;
#pragma unroll 10
        for (int k = 0; k < 50; k++) lik = fmaf(w[k], Pr[(size_t)k * Vv], lik);
        acc = __logf(lik + 1e-6f) * bows[d * Vv + v];
    }
    float tot = blockReduceSum(acc, sm);
    if (tid == 0) atomicAdd(&g_scalars[0], tot);
}

__global__ void finalizeK(float* __restrict__ out) {
    if (threadIdx.x == 0) {
        out[0] = -g_scalars[0];
        out[1] = g_scalars[1];
        out[2] = g_scalars[2];
        out[3] = g_scalars[3];
    }
}

// ---------------- host orchestration ----------------------------------------
extern "C" void kernel_launch(void* const* d_in, const int* in_sizes, int n_in,
                              void* d_out, int out_size) {
    const float* bows    = (const float*)d_in[0];
    const float* rnn_inp = (const float*)d_in[1];
    const int*   times   = (const int*)d_in[2];
    const int*   sources = (const int*)d_in[3];
    const float* rho     = (const float*)d_in[4];
    const float* lam     = (const float*)d_in[5];
    const float* mu_q    = (const float*)d_in[6];
    const float* ls_q    = (const float*)d_in[7];
    const float* W_t1    = (const float*)d_in[8];
    const float* b_t1    = (const float*)d_in[9];
    const float* W_t2    = (const float*)d_in[10];
    const float* b_t2    = (const float*)d_in[11];
    const float* W_mu_th = (const float*)d_in[12];
    const float* b_mu_th = (const float*)d_in[13];
    const float* W_ls_th = (const float*)d_in[14];
    const float* b_ls_th = (const float*)d_in[15];
    const float* W_em    = (const float*)d_in[16];
    const float* b_em    = (const float*)d_in[17];
    const float* Wih0    = (const float*)d_in[18];
    const float* Whh0    = (const float*)d_in[19];
    const float* bl0     = (const float*)d_in[20];
    const float* Wih1    = (const float*)d_in[21];
    const float* Whh1    = (const float*)d_in[22];
    const float* bl1     = (const float*)d_in[23];
    const float* W_mu_e  = (const float*)d_in[24];
    const float* b_mu_e  = (const float*)d_in[25];
    const float* W_ls_e  = (const float*)d_in[26];
    const float* b_ls_e  = (const float*)d_in[27];

    float *pX, *pXw0, *pXw1, *pHs0, *pHs1, *pCat, *pH1, *pH2, *pMuth, *pLsth, *pP, *pS;
    __nv_bfloat16 *pAbf, *pRhoBf;
    cudaGetSymbolAddress((void**)&pX, g_x);
    cudaGetSymbolAddress((void**)&pXw0, g_xw0);
    cudaGetSymbolAddress((void**)&pXw1, g_xw1);
    cudaGetSymbolAddress((void**)&pHs0, g_hs0);
    cudaGetSymbolAddress((void**)&pHs1, g_hs1);
    cudaGetSymbolAddress((void**)&pCat, g_cat);
    cudaGetSymbolAddress((void**)&pH1, g_h1);
    cudaGetSymbolAddress((void**)&pH2, g_h2);
    cudaGetSymbolAddress((void**)&pMuth, g_muth);
    cudaGetSymbolAddress((void**)&pLsth, g_lsth);
    cudaGetSymbolAddress((void**)&pP, g_P);
    cudaGetSymbolAddress((void**)&pS, g_S);
    cudaGetSymbolAddress((void**)&pAbf, g_Abf);
    cudaGetSymbolAddress((void**)&pRhoBf, g_rhoBf);

    cudaFuncSetAttribute(lstmK, cudaFuncAttributeMaxDynamicSharedMemorySize, LSTM_SMEM);
    cudaFuncSetAttribute(gemmExpMMA, cudaFuncAttributeMaxDynamicSharedMemorySize, GEMM_SMEM);
    cudaFuncSetAttribute(etaScanK, cudaFuncAttributeMaxDynamicSharedMemorySize, ETA_SMEM);

    // Launches 1-3: deps of the big GEMM; launch 4 = gemmExpMMA (ncu sample target)
    zeroAllK<<<256, 256>>>();
    buildABfK<<<2048, 256>>>(mu_q, lam, times, sources);
    rhoBfK<<<512, 256>>>(rho);
    gemmExpMMA<<<dim3(24, 100), 256, GEMM_SMEM>>>(pAbf, pRhoBf, pP, pS);

    klAlphaK<<<256, 256>>>(mu_q, ls_q);

    // x = rnn_inp @ W_em + b_em
    gemmNN<<<dim3(4, 1, 8), 256>>>(rnn_inp, W_em, pX, 50, 200, 3000, 384);
    biasActK<<<40, 256>>>(pX, b_em, 50, 200, 0);

    // LSTM layer 0
    gemmNN<<<dim3(13, 1, 1), 256>>>(pX, Wih0, pXw0, 50, 800, 200, 200);
    biasActK<<<160, 256>>>(pXw0, bl0, 50, 800, 0);
    lstmK<<<4, 256, LSTM_SMEM>>>(pXw0, Whh0, pHs0);

    // LSTM layer 1
    gemmNN<<<dim3(13, 1, 1), 256>>>(pHs0, Wih1, pXw1, 50, 800, 200, 200);
    biasActK<<<160, 256>>>(pXw1, bl1, 50, 800, 0);
    lstmK<<<4, 256, LSTM_SMEM>>>(pXw1, Whh1, pHs1);

    // eta scan
    etaScanK<<<1, 512, ETA_SMEM>>>(pHs1, W_mu_e, b_mu_e, W_ls_e, b_ls_e);

    // theta MLP
    buildCatK<<<1024, 256>>>(bows, times);
    gemmNN<<<dim3(13, 4, 4), 256>>>(pCat, W_t1, pH1, 256, 800, 3050, 768);
    biasActK<<<800, 256>>>(pH1, b_t1, 256, 800, 1);
    gemmNN<<<dim3(13, 4, 2), 256>>>(pH1, W_t2, pH2, 256, 800, 800, 400);
    biasActK<<<800, 256>>>(pH2, b_t2, 256, 800, 1);
    gemmNN<<<dim3(1, 4, 8), 256>>>(pH2, W_mu_th, pMuth, 256, 50, 800, 112);
    biasActK<<<50, 256>>>(pMuth, b_mu_th, 256, 50, 0);
    gemmNN<<<dim3(1, 4, 8), 256>>>(pH2, W_ls_th, pLsth, 256, 50, 800, 112);
    biasActK<<<50, 256>>>(pLsth, b_ls_th, 256, 50, 0);
    thetaKlK<<<256, 64>>>(times);

    // lik/nll over P
    likNllK<<<dim3(12, 256), 256>>>(bows);

    finalizeK<<<1, 32>>>((float*)d_out);
}